// round 13
// baseline (speedup 1.0000x reference)
#include <cuda_runtime.h>
#include <cuda_fp16.h>
#include <math.h>
#include <stdint.h>

// ---------------- problem constants ----------------
#define BB 2
#define SS 2048
#define HH 2304
#define NH 8
#define NKV 4
#define HD 256
#define FF 9216
#define MROWS (BB * SS)          // 4096
#define QC (NH * HD)             // 2048
#define KC (NKV * HD)            // 1024
#define SOFTCAP 50.0f
#define ATT_SCALE 0.0625f
#define RMS_EPS 1e-6f

typedef __half f16;

// ---------------- scratch (device globals; no allocations) ----------------
#define DEVBUF __device__ __align__(256)
DEVBUF f16   s_h   [(size_t)MROWS * HH];
DEVBUF float g_q   [(size_t)MROWS * QC];
DEVBUF float g_k   [(size_t)MROWS * KC];
DEVBUF float g_v   [(size_t)MROWS * KC];
DEVBUF f16   s_q_hi[(size_t)MROWS * QC];  DEVBUF f16 s_q_lo[(size_t)MROWS * QC];
DEVBUF f16   s_k_hi[(size_t)MROWS * KC];  DEVBUF f16 s_k_lo[(size_t)MROWS * KC];
DEVBUF f16   s_vt  [(size_t)MROWS * KC];
DEVBUF float g_sc  [(size_t)BB * NH * SS * SS];
DEVBUF f16   s_p   [(size_t)BB * NH * SS * SS];
DEVBUF f16   s_o   [(size_t)MROWS * QC];
DEVBUF float g_attn[(size_t)MROWS * HH];
DEVBUF float g_h2  [(size_t)MROWS * HH];
DEVBUF f16   s_f   [(size_t)MROWS * HH];
DEVBUF float g_gate[(size_t)MROWS * FF];
DEVBUF float g_up  [(size_t)MROWS * FF];
DEVBUF f16   s_a   [(size_t)MROWS * FF];
DEVBUF float g_mlp [(size_t)MROWS * HH];
// transposed weights ([N,K] K-major, single fp16)
DEVBUF f16 w_qt[(size_t)QC * HH];
DEVBUF f16 w_kt[(size_t)KC * HH];
DEVBUF f16 w_vt[(size_t)KC * HH];
DEVBUF f16 w_ot[(size_t)HH * QC];
DEVBUF f16 w_gt[(size_t)FF * HH];
DEVBUF f16 w_ut[(size_t)FF * HH];
DEVBUF f16 w_dt[(size_t)HH * FF];

// ---------------- PTX helpers ----------------
__device__ __forceinline__ uint32_t smem_u32(const void* p) {
    uint32_t a;
    asm("{ .reg .u64 t; cvta.to.shared.u64 t, %1; cvt.u32.u64 %0, t; }" : "=r"(a) : "l"(p));
    return a;
}
__device__ __forceinline__ void cp16(uint32_t saddr, const void* g) {
    asm volatile("cp.async.cg.shared.global [%0], [%1], 16;" :: "r"(saddr), "l"(g));
}
#define CP_COMMIT() asm volatile("cp.async.commit_group;" ::: "memory")

__device__ __forceinline__ void ldsm_x4(uint32_t (&r)[4], uint32_t addr) {
    asm volatile("ldmatrix.sync.aligned.m8n8.x4.shared.b16 {%0,%1,%2,%3}, [%4];"
                 : "=r"(r[0]), "=r"(r[1]), "=r"(r[2]), "=r"(r[3]) : "r"(addr));
}
__device__ __forceinline__ void mma_f16(float (&c)[4], const uint32_t (&a)[4],
                                        uint32_t b0, uint32_t b1) {
    asm volatile(
        "mma.sync.aligned.m16n8k16.row.col.f32.f16.f16.f32 "
        "{%0,%1,%2,%3}, {%4,%5,%6,%7}, {%8,%9}, {%0,%1,%2,%3};"
        : "+f"(c[0]), "+f"(c[1]), "+f"(c[2]), "+f"(c[3])
        : "r"(a[0]), "r"(a[1]), "r"(a[2]), "r"(a[3]), "r"(b0), "r"(b1));
}

__device__ __forceinline__ void split2h(float v, f16* hi, f16* lo) {
    f16 h = __float2half_rn(v);
    *hi = h;
    *lo = __float2half_rn(v - __half2float(h));
}

// ---------------- GEMM config ----------------
// CTA tile 128(M) x 256(N) x 32(K-chunk), 256 threads (8 warps, 2x4),
// warp tile 64x64, cp.async multi-stage, LDS_T=40 (conflict-free ldmatrix).
#define LDS_T  40
#define TA_B   (128 * LDS_T * 2)          // 10240 B
#define TB_B   (256 * LDS_T * 2)          // 20480 B
#define SMEM_G1 (4 * (TA_B + TB_B))       // 122880 B (1-pass, 4 stages)
#define SMEM_G3 (3 * 2 * (TA_B + TB_B))   // 184320 B (3-pass, 3 stages)

// C[128 x 256 tile]. PASSES=1: C = A @ B^T (single fp16 operands).
// PASSES=3: C = (Ahi+Alo) @ (Bhi+Blo)^T  (drops lo*lo).
// OUT_HALF: write fp16 Ch instead of fp32 C.
template<int PASSES, bool OUT_HALF>
__device__ __forceinline__ void gemm_body(
    const f16* __restrict__ Ahi, const f16* __restrict__ Alo,
    const f16* __restrict__ Bhi, const f16* __restrict__ Blo,
    float* __restrict__ C, f16* __restrict__ Ch,
    int K, int lda, int ldb, int ldc) {
    constexpr int SAHI = 0;
    constexpr int SALO = (PASSES == 3) ? TA_B : 0;
    constexpr int SBHI = (PASSES == 3) ? 2 * TA_B : TA_B;
    constexpr int SBLO = (PASSES == 3) ? 2 * TA_B + TB_B : 0;
    constexpr int STAGE = (PASSES == 3) ? 2 * (TA_B + TB_B) : (TA_B + TB_B);
    constexpr int NST = (PASSES == 3) ? 3 : 4;

    extern __shared__ char smem[];
    const uint32_t sb = smem_u32(smem);
    const int tid = threadIdx.x;
    const int lid = tid & 31;
    const int wid = tid >> 5;            // 0..7
    const int warp_m = wid & 1;          // 2 M-warps
    const int warp_n = wid >> 1;         // 4 N-warps
    const int m0 = blockIdx.y * 128, n0 = blockIdx.x * 256;

    float acc[4][8][4];
#pragma unroll
    for (int mt = 0; mt < 4; mt++)
#pragma unroll
        for (int nt = 0; nt < 8; nt++)
#pragma unroll
            for (int j = 0; j < 4; j++) acc[mt][nt][j] = 0.0f;

    const int nch = K >> 5;

    auto load_chunk = [&](int ch) {
        const int k0 = ch << 5;
        const uint32_t base = sb + (ch % NST) * STAGE;
#pragma unroll
        for (int i = 0; i < 2; i++) {   // A: 128 rows x 32 cols = 512 x 16B lines
            int idx = i * 256 + tid;
            int row = idx >> 2, c4 = idx & 3;
            uint32_t so = (uint32_t)(row * LDS_T + c4 * 8) * 2;
            size_t ga = (size_t)(m0 + row) * lda + k0 + c4 * 8;
            cp16(base + SAHI + so, Ahi + ga);
            if (PASSES == 3) cp16(base + SALO + so, Alo + ga);
        }
#pragma unroll
        for (int i = 0; i < 4; i++) {   // B: 256 rows = 1024 x 16B lines
            int idx = i * 256 + tid;
            int row = idx >> 2, c4 = idx & 3;
            uint32_t so = (uint32_t)(row * LDS_T + c4 * 8) * 2;
            size_t gb = (size_t)(n0 + row) * ldb + k0 + c4 * 8;
            cp16(base + SBHI + so, Bhi + gb);
            if (PASSES == 3) cp16(base + SBLO + so, Blo + gb);
        }
    };

    // prologue: NST-1 chunks in flight
#pragma unroll
    for (int i = 0; i < NST - 1; i++) {
        if (i < nch) load_chunk(i);
        CP_COMMIT();
    }

    for (int ch = 0; ch < nch; ch++) {
        asm volatile("cp.async.wait_group %0;" :: "n"(NST - 2) : "memory");
        __syncthreads();
        if (ch + NST - 1 < nch) load_chunk(ch + NST - 1);
        CP_COMMIT();

        const uint32_t base = sb + (ch % NST) * STAGE;
        const uint32_t sA_hi = base + SAHI, sA_lo = base + SALO;
        const uint32_t sB_hi = base + SBHI, sB_lo = base + SBLO;

#pragma unroll
        for (int ks = 0; ks < 32; ks += 16) {
            const int col = ks + ((lid >> 4) << 3);
            const uint32_t a_off = (uint32_t)((warp_m * 64 + (lid & 15)) * LDS_T + col) * 2;
            const uint32_t b_off = (uint32_t)((warp_n * 64 + (lid & 15)) * LDS_T + col) * 2;

            uint32_t Ah[4][4], Bf[4][4];
#pragma unroll
            for (int p = 0; p < 4; p++) ldsm_x4(Ah[p], sA_hi + a_off + p * 16 * LDS_T * 2);
#pragma unroll
            for (int p = 0; p < 4; p++) ldsm_x4(Bf[p], sB_hi + b_off + p * 16 * LDS_T * 2);

            // pass 1: hi * hi
#pragma unroll
            for (int mt = 0; mt < 4; mt++)
#pragma unroll
                for (int nt = 0; nt < 8; nt++)
                    mma_f16(acc[mt][nt], Ah[mt], Bf[nt >> 1][nt & 1], Bf[nt >> 1][(nt & 1) + 2]);

            if (PASSES == 3) {
                // pass 2: lo * hi
#pragma unroll
                for (int p = 0; p < 4; p++) {
                    uint32_t Al[4];
                    ldsm_x4(Al, sA_lo + a_off + p * 16 * LDS_T * 2);
#pragma unroll
                    for (int nt = 0; nt < 8; nt++)
                        mma_f16(acc[p][nt], Al, Bf[nt >> 1][nt & 1], Bf[nt >> 1][(nt & 1) + 2]);
                }
                // pass 3: hi * lo
#pragma unroll
                for (int p = 0; p < 4; p++) ldsm_x4(Bf[p], sB_lo + b_off + p * 16 * LDS_T * 2);
#pragma unroll
                for (int mt = 0; mt < 4; mt++)
#pragma unroll
                    for (int nt = 0; nt < 8; nt++)
                        mma_f16(acc[mt][nt], Ah[mt], Bf[nt >> 1][nt & 1], Bf[nt >> 1][(nt & 1) + 2]);
            }
        }
        __syncthreads();
    }

    // epilogue
#pragma unroll
    for (int mt = 0; mt < 4; mt++) {
        const int row = m0 + warp_m * 64 + mt * 16 + (lid >> 2);
#pragma unroll
        for (int nt = 0; nt < 8; nt++) {
            const int colx = n0 + warp_n * 64 + nt * 8 + (lid & 3) * 2;
            if (OUT_HALF) {
                __half2 v0, v1;
                v0.x = __float2half_rn(acc[mt][nt][0]);
                v0.y = __float2half_rn(acc[mt][nt][1]);
                v1.x = __float2half_rn(acc[mt][nt][2]);
                v1.y = __float2half_rn(acc[mt][nt][3]);
                *(__half2*)(Ch + (size_t)row * ldc + colx)       = v0;
                *(__half2*)(Ch + (size_t)(row + 8) * ldc + colx) = v1;
            } else {
                *(float2*)(C + (size_t)row * ldc + colx) =
                    make_float2(acc[mt][nt][0], acc[mt][nt][1]);
                *(float2*)(C + (size_t)(row + 8) * ldc + colx) =
                    make_float2(acc[mt][nt][2], acc[mt][nt][3]);
            }
        }
    }
}

// single-pass fp16 GEMM, fp32 out
__global__ void __launch_bounds__(256, 1) k_gemm(
    const f16* __restrict__ A, const f16* __restrict__ B,
    float* __restrict__ C, int K, int lda, int ldb, int ldc) {
    gemm_body<1, false>(A, nullptr, B, nullptr, C, nullptr, K, lda, ldb, ldc);
}

// causal QK: 3-pass fp16 split (exact-ish scores), skip upper-triangle tiles
__global__ void __launch_bounds__(256, 1) k_qk() {
    if (2 * blockIdx.x > blockIdx.y) return;
    int bh = blockIdx.z;
    int b = bh >> 3, h = bh & 7, kv = h >> 1;
    gemm_body<3, false>(s_q_hi + (size_t)b * SS * QC + h * HD,
                        s_q_lo + (size_t)b * SS * QC + h * HD,
                        s_k_hi + (size_t)b * SS * KC + kv * HD,
                        s_k_lo + (size_t)b * SS * KC + kv * HD,
                        g_sc + (size_t)bh * SS * SS, nullptr,
                        HD, QC, KC, SS);
}

// PV: single-pass fp16, causal K-limit, fp16 out (o)
__global__ void __launch_bounds__(256, 1) k_pv() {
    int bh = blockIdx.z;
    int b = bh >> 3, h = bh & 7, kv = h >> 1;
    int klim = (blockIdx.y + 1) * 128;
    if (klim > SS) klim = SS;
    gemm_body<1, true>(s_p + (size_t)bh * SS * SS, nullptr,
                       s_vt + (size_t)(b * NKV + kv) * HD * SS, nullptr,
                       nullptr, s_o + (size_t)b * SS * QC + h * HD,
                       klim, SS, SS, QC);
}

// ---------------- transpose / elementwise ----------------
// transpose: fp32 [R,C] -> fp16 [C,R]
__global__ void __launch_bounds__(256) k_t16(const float* __restrict__ in,
                                             f16* __restrict__ o, int R, int C) {
    __shared__ float t[32][33];
    int c0 = blockIdx.x * 32, r0 = blockIdx.y * 32;
    int tx = threadIdx.x & 31, ty = threadIdx.x >> 5;
#pragma unroll
    for (int i = 0; i < 4; i++)
        t[ty + i * 8][tx] = in[(size_t)(r0 + ty + i * 8) * C + c0 + tx];
    __syncthreads();
#pragma unroll
    for (int i = 0; i < 4; i++)
        o[(size_t)(c0 + ty + i * 8) * R + r0 + tx] = __float2half_rn(t[tx][ty + i * 8]);
}

// rmsnorm -> fp16
__global__ void __launch_bounds__(256) k_rms16(const float* __restrict__ x,
                                               const float* __restrict__ g,
                                               f16* __restrict__ o) {
    int row = blockIdx.x;
    const float* xr = x + (size_t)row * HH;
    float s = 0.0f;
    for (int i = threadIdx.x; i < HH; i += 256) { float v = xr[i]; s = fmaf(v, v, s); }
    __shared__ float red[256];
    red[threadIdx.x] = s;
    __syncthreads();
    for (int off = 128; off > 0; off >>= 1) {
        if (threadIdx.x < off) red[threadIdx.x] += red[threadIdx.x + off];
        __syncthreads();
    }
    float rstd = rsqrtf(red[0] * (1.0f / HH) + RMS_EPS);
    size_t base = (size_t)row * HH;
    for (int i = threadIdx.x; i < HH; i += 256)
        o[base + i] = __float2half_rn(xr[i] * rstd * (1.0f + g[i]));
}

// out = res + rmsnorm(y, g)  (fp32)
__global__ void __launch_bounds__(256) k_add_rms(const float* __restrict__ res,
                                                 const float* __restrict__ y,
                                                 const float* __restrict__ g,
                                                 float* __restrict__ out) {
    int row = blockIdx.x;
    const float* yr = y + (size_t)row * HH;
    float s = 0.0f;
    for (int i = threadIdx.x; i < HH; i += 256) { float v = yr[i]; s = fmaf(v, v, s); }
    __shared__ float red[256];
    red[threadIdx.x] = s;
    __syncthreads();
    for (int off = 128; off > 0; off >>= 1) {
        if (threadIdx.x < off) red[threadIdx.x] += red[threadIdx.x + off];
        __syncthreads();
    }
    float rstd = rsqrtf(red[0] * (1.0f / HH) + RMS_EPS);
    const float* rr = res + (size_t)row * HH;
    float* orow = out + (size_t)row * HH;
    for (int i = threadIdx.x; i < HH; i += 256)
        orow[i] = rr[i] + yr[i] * rstd * (1.0f + g[i]);
}

// RoPE on fp32 q/k -> fp16 hi/lo split buffers
__global__ void __launch_bounds__(256) k_rope_split() {
    int idx = blockIdx.x * 256 + threadIdx.x;            // < MROWS*12*128
    int j = idx & 127;
    int hd = (idx >> 7) % 12;
    int row = idx / (12 * 128);
    int pos = row & (SS - 1);
    float inv = __powf(10000.0f, -(float)(2 * j) * (1.0f / HD));
    float fr = (float)pos * inv;
    float sn, cs;
    sincosf(fr, &sn, &cs);
    const float* base;
    f16 *ohi, *olo;
    size_t off;
    if (hd < 8) {
        off = (size_t)row * QC + hd * HD;
        base = g_q + off; ohi = s_q_hi + off; olo = s_q_lo + off;
    } else {
        off = (size_t)row * KC + (hd - 8) * HD;
        base = g_k + off; ohi = s_k_hi + off; olo = s_k_lo + off;
    }
    float v0 = base[j], v1 = base[j + 128];
    split2h(v0 * cs - v1 * sn, ohi + j, olo + j);
    split2h(v1 * cs + v0 * sn, ohi + j + 128, olo + j + 128);
}

// V: fp32 [B,S,NKV,HD] -> fp16 transposed [B*NKV, HD, S]
__global__ void __launch_bounds__(256) k_vtrans() {
    __shared__ float t[32][33];
    int bkv = blockIdx.z;
    int b = bkv >> 2, kv = bkv & 3;
    int d0 = blockIdx.x * 32, s0 = blockIdx.y * 32;
    int tx = threadIdx.x & 31, ty = threadIdx.x >> 5;
#pragma unroll
    for (int i = 0; i < 4; i++)
        t[ty + i * 8][tx] = g_v[(size_t)(b * SS + s0 + ty + i * 8) * KC + kv * HD + d0 + tx];
    __syncthreads();
#pragma unroll
    for (int i = 0; i < 4; i++) {
        size_t o = (size_t)bkv * HD * SS + (size_t)(d0 + ty + i * 8) * SS + s0 + tx;
        s_vt[o] = __float2half_rn(t[tx][ty + i * 8]);
    }
}

// softmax (softcap + causal): only j <= qi read; zero-fill to 128-boundary; fp16 out
__global__ void __launch_bounds__(256) k_softmax() {
    int r = blockIdx.x;                 // bh*SS + qi
    int qi = r & (SS - 1);
    int nr = ((qi >> 7) + 1) << 7;
    const float* row = g_sc + (size_t)r * SS;
    int t = threadIdx.x;
    float vals[8];
    float mx = -1e30f;
    int it = 0;
    for (int j = t; j < nr; j += 256, it++) {
        float s = -1e30f;
        if (j <= qi) {
            s = row[j] * ATT_SCALE;
            s = SOFTCAP * tanhf(s * (1.0f / SOFTCAP));
            mx = fmaxf(mx, s);
        }
        vals[it] = s;
    }
    __shared__ float red[256];
    red[t] = mx;
    __syncthreads();
    for (int off = 128; off > 0; off >>= 1) {
        if (t < off) red[t] = fmaxf(red[t], red[t + off]);
        __syncthreads();
    }
    mx = red[0];
    __syncthreads();
    float sum = 0.0f;
    it = 0;
    for (int j = t; j < nr; j += 256, it++) {
        float e = (vals[it] > -1e29f) ? __expf(vals[it] - mx) : 0.0f;
        vals[it] = e;
        sum += e;
    }
    red[t] = sum;
    __syncthreads();
    for (int off = 128; off > 0; off >>= 1) {
        if (t < off) red[t] += red[t + off];
        __syncthreads();
    }
    float inv = 1.0f / red[0];
    size_t base = (size_t)r * SS;
    it = 0;
    for (int j = t; j < nr; j += 256, it++)
        s_p[base + j] = __float2half_rn(vals[it] * inv);
}

// GeGLU: act = gelu_tanh(gate) * up -> fp16
__global__ void __launch_bounds__(256) k_geglu() {
    size_t i = (size_t)blockIdx.x * 256 + threadIdx.x;
    float x = g_gate[i];
    float u = g_up[i];
    const float c0 = 0.7978845608028654f;
    float inner = c0 * fmaf(0.044715f * x * x, x, x);
    float act = 0.5f * x * (1.0f + tanhf(inner)) * u;
    s_a[i] = __float2half_rn(act);
}

// ---------------- launch ----------------
extern "C" void kernel_launch(void* const* d_in, const int* in_sizes, int n_in,
                              void* d_out, int out_size) {
    const float* x      = (const float*)d_in[0];
    // d_in[1] = mask (pure causal; applied analytically)
    const float* wq     = (const float*)d_in[2];
    const float* wk     = (const float*)d_in[3];
    const float* wv     = (const float*)d_in[4];
    const float* wo     = (const float*)d_in[5];
    const float* w_gate = (const float*)d_in[6];
    const float* w_up   = (const float*)d_in[7];
    const float* w_down = (const float*)d_in[8];
    const float* gin    = (const float*)d_in[9];
    const float* gpa    = (const float*)d_in[10];
    const float* gpf    = (const float*)d_in[11];
    const float* gpff   = (const float*)d_in[12];
    float* out = (float*)d_out;

    cudaFuncSetAttribute(k_gemm, cudaFuncAttributeMaxDynamicSharedMemorySize, SMEM_G1);
    cudaFuncSetAttribute(k_pv,   cudaFuncAttributeMaxDynamicSharedMemorySize, SMEM_G1);
    cudaFuncSetAttribute(k_qk,   cudaFuncAttributeMaxDynamicSharedMemorySize, SMEM_G3);

#define SYM(p, s) void* p; cudaGetSymbolAddress(&p, s)
    SYM(p_h, s_h);
    SYM(p_q, g_q);  SYM(p_k, g_k);  SYM(p_v, g_v);
    SYM(p_o, s_o);
    SYM(p_attn, g_attn); SYM(p_h2, g_h2); SYM(p_f, s_f);
    SYM(p_gate, g_gate); SYM(p_up, g_up); SYM(p_a, s_a);
    SYM(p_mlp, g_mlp);
    SYM(p_wq, w_qt); SYM(p_wk, w_kt); SYM(p_wv, w_vt); SYM(p_wo, w_ot);
    SYM(p_wg, w_gt); SYM(p_wu, w_ut); SYM(p_wd, w_dt);
#undef SYM

    // weight transposes (fp32 [K,N] -> fp16 [N,K])
    k_t16<<<dim3(QC / 32, HH / 32), 256>>>(wq, (f16*)p_wq, HH, QC);
    k_t16<<<dim3(KC / 32, HH / 32), 256>>>(wk, (f16*)p_wk, HH, KC);
    k_t16<<<dim3(KC / 32, HH / 32), 256>>>(wv, (f16*)p_wv, HH, KC);
    k_t16<<<dim3(HH / 32, QC / 32), 256>>>(wo, (f16*)p_wo, QC, HH);
    k_t16<<<dim3(FF / 32, HH / 32), 256>>>(w_gate, (f16*)p_wg, HH, FF);
    k_t16<<<dim3(FF / 32, HH / 32), 256>>>(w_up,   (f16*)p_wu, HH, FF);
    k_t16<<<dim3(HH / 32, FF / 32), 256>>>(w_down, (f16*)p_wd, FF, HH);

    // h = rmsnorm(x, g_in) -> fp16
    k_rms16<<<MROWS, 256>>>(x, gin, (f16*)p_h);

    // q/k/v projections (fp32 out)
    k_gemm<<<dim3(QC / 256, MROWS / 128), 256, SMEM_G1>>>(
        (f16*)p_h, (f16*)p_wq, (float*)p_q, HH, HH, HH, QC);
    k_gemm<<<dim3(KC / 256, MROWS / 128), 256, SMEM_G1>>>(
        (f16*)p_h, (f16*)p_wk, (float*)p_k, HH, HH, HH, KC);
    k_gemm<<<dim3(KC / 256, MROWS / 128), 256, SMEM_G1>>>(
        (f16*)p_h, (f16*)p_wv, (float*)p_v, HH, HH, HH, KC);

    // RoPE -> q/k fp16 hi/lo; V transpose -> fp16
    k_rope_split<<<(MROWS * 12 * 128) / 256, 256>>>();
    k_vtrans<<<dim3(HD / 32, SS / 32, BB * NKV), 256>>>();

    // scores = q @ k^T (3-pass, causal tiles only)
    k_qk<<<dim3(SS / 256, SS / 128, BB * NH), 256, SMEM_G3>>>();

    // softcap + causal + softmax -> p fp16
    k_softmax<<<BB * NH * SS, 256>>>();

    // o = p @ v (causal K-limit, fp16 out)
    k_pv<<<dim3(HD / 256, SS / 128, BB * NH), 256, SMEM_G1>>>();

    // attn_out = o @ wo
    k_gemm<<<dim3(HH / 256, MROWS / 128), 256, SMEM_G1>>>(
        (f16*)p_o, (f16*)p_wo, (float*)p_attn, QC, QC, QC, HH);

    // h2 = x + rmsnorm(attn); f = rmsnorm(h2) -> fp16
    k_add_rms<<<MROWS, 256>>>(x, (float*)p_attn, gpa, (float*)p_h2);
    k_rms16<<<MROWS, 256>>>((float*)p_h2, gpf, (f16*)p_f);

    // gate/up
    k_gemm<<<dim3(FF / 256, MROWS / 128), 256, SMEM_G1>>>(
        (f16*)p_f, (f16*)p_wg, (float*)p_gate, HH, HH, HH, FF);
    k_gemm<<<dim3(FF / 256, MROWS / 128), 256, SMEM_G1>>>(
        (f16*)p_f, (f16*)p_wu, (float*)p_up, HH, HH, HH, FF);

    // GeGLU -> fp16
    k_geglu<<<(int)(((size_t)MROWS * FF) / 256), 256>>>();

    // mlp = act @ w_down
    k_gemm<<<dim3(HH / 256, MROWS / 128), 256, SMEM_G1>>>(
        (f16*)p_a, (f16*)p_wd, (float*)p_mlp, FF, FF, FF, HH);

    // out = h2 + rmsnorm(mlp)
    k_add_rms<<<MROWS, 256>>>((float*)p_h2, (float*)p_mlp, gpff, out);
}

// round 14
// speedup vs baseline: 1.0974x; 1.0974x over previous
#include <cuda_runtime.h>
#include <cuda_fp16.h>
#include <math.h>
#include <stdint.h>

// ---------------- problem constants ----------------
#define BB 2
#define SS 2048
#define HH 2304
#define NH 8
#define NKV 4
#define HD 256
#define FF 9216
#define MROWS (BB * SS)          // 4096
#define QC (NH * HD)             // 2048
#define KC (NKV * HD)            // 1024
#define SOFTCAP 50.0f
#define ATT_SCALE 0.0625f
#define RMS_EPS 1e-6f

typedef __half f16;

// ---------------- scratch (device globals; no allocations) ----------------
#define DEVBUF __device__ __align__(256)
DEVBUF f16   s_h   [(size_t)MROWS * HH];
DEVBUF float g_q   [(size_t)MROWS * QC];
DEVBUF float g_k   [(size_t)MROWS * KC];
DEVBUF float g_v   [(size_t)MROWS * KC];
DEVBUF f16   s_q_hi[(size_t)MROWS * QC];  DEVBUF f16 s_q_lo[(size_t)MROWS * QC];
DEVBUF f16   s_k_hi[(size_t)MROWS * KC];  DEVBUF f16 s_k_lo[(size_t)MROWS * KC];
DEVBUF f16   s_vt  [(size_t)MROWS * KC];
DEVBUF float g_sc  [(size_t)BB * NH * SS * SS];
DEVBUF f16   s_p   [(size_t)BB * NH * SS * SS];
DEVBUF f16   s_o   [(size_t)MROWS * QC];
DEVBUF float g_attn[(size_t)MROWS * HH];
DEVBUF float g_h2  [(size_t)MROWS * HH];
DEVBUF f16   s_f   [(size_t)MROWS * HH];
DEVBUF float g_gate[(size_t)MROWS * FF];
DEVBUF float g_up  [(size_t)MROWS * FF];
DEVBUF f16   s_a   [(size_t)MROWS * FF];
DEVBUF float g_mlp [(size_t)MROWS * HH];
// transposed weights ([N,K] K-major, single fp16)
DEVBUF f16 w_qt[(size_t)QC * HH];
DEVBUF f16 w_kt[(size_t)KC * HH];
DEVBUF f16 w_vt[(size_t)KC * HH];
DEVBUF f16 w_ot[(size_t)HH * QC];
DEVBUF f16 w_gt[(size_t)FF * HH];
DEVBUF f16 w_ut[(size_t)FF * HH];
DEVBUF f16 w_dt[(size_t)HH * FF];

// ---------------- PTX helpers ----------------
__device__ __forceinline__ uint32_t smem_u32(const void* p) {
    uint32_t a;
    asm("{ .reg .u64 t; cvta.to.shared.u64 t, %1; cvt.u32.u64 %0, t; }" : "=r"(a) : "l"(p));
    return a;
}
__device__ __forceinline__ void cp16(uint32_t saddr, const void* g) {
    asm volatile("cp.async.cg.shared.global [%0], [%1], 16;" :: "r"(saddr), "l"(g));
}
#define CP_COMMIT() asm volatile("cp.async.commit_group;" ::: "memory")

__device__ __forceinline__ void ldsm_x4(uint32_t (&r)[4], uint32_t addr) {
    asm volatile("ldmatrix.sync.aligned.m8n8.x4.shared.b16 {%0,%1,%2,%3}, [%4];"
                 : "=r"(r[0]), "=r"(r[1]), "=r"(r[2]), "=r"(r[3]) : "r"(addr));
}
__device__ __forceinline__ void mma_f16(float (&c)[4], const uint32_t (&a)[4],
                                        uint32_t b0, uint32_t b1) {
    asm volatile(
        "mma.sync.aligned.m16n8k16.row.col.f32.f16.f16.f32 "
        "{%0,%1,%2,%3}, {%4,%5,%6,%7}, {%8,%9}, {%0,%1,%2,%3};"
        : "+f"(c[0]), "+f"(c[1]), "+f"(c[2]), "+f"(c[3])
        : "r"(a[0]), "r"(a[1]), "r"(a[2]), "r"(a[3]), "r"(b0), "r"(b1));
}

__device__ __forceinline__ void split2h(float v, f16* hi, f16* lo) {
    f16 h = __float2half_rn(v);
    *hi = h;
    *lo = __float2half_rn(v - __half2float(h));
}

// ---------------- GEMM config ----------------
// CTA tile 128(M) x 256(N), 512 threads (16 warps, 4(M) x 2(N)), warp tile 32x64.
// PASSES=1: K-chunk 64, LDS_T=72, 3 stages.  PASSES=3: K-chunk 32, LDS_T=40, 3 stages.
#define LT1    72
#define TA1_B  (128 * LT1 * 2)            // 18432 B
#define TB1_B  (256 * LT1 * 2)            // 36864 B
#define SMEM_G1 (3 * (TA1_B + TB1_B))     // 165888 B

#define LT3    40
#define TA3_B  (128 * LT3 * 2)            // 10240 B
#define TB3_B  (256 * LT3 * 2)            // 20480 B
#define SMEM_G3 (3 * 2 * (TA3_B + TB3_B)) // 184320 B

// C[128 x 256 tile]. PASSES=1: C = A @ B^T (single fp16 operands).
// PASSES=3: C = (Ahi+Alo) @ (Bhi+Blo)^T  (drops lo*lo).
// OUT_HALF: write fp16 Ch instead of fp32 C.
template<int PASSES, bool OUT_HALF>
__device__ __forceinline__ void gemm_body(
    const f16* __restrict__ Ahi, const f16* __restrict__ Alo,
    const f16* __restrict__ Bhi, const f16* __restrict__ Blo,
    float* __restrict__ C, f16* __restrict__ Ch,
    int K, int lda, int ldb, int ldc) {
    constexpr int KCH  = (PASSES == 3) ? 32 : 64;      // K per chunk
    constexpr int LT   = (PASSES == 3) ? LT3 : LT1;    // padded smem row stride
    constexpr int TA_B = 128 * LT * 2;
    constexpr int TB_B = 256 * LT * 2;
    constexpr int SAHI = 0;
    constexpr int SALO = (PASSES == 3) ? TA_B : 0;
    constexpr int SBHI = (PASSES == 3) ? 2 * TA_B : TA_B;
    constexpr int SBLO = (PASSES == 3) ? 2 * TA_B + TB_B : 0;
    constexpr int STAGE = (PASSES == 3) ? 2 * (TA_B + TB_B) : (TA_B + TB_B);
    constexpr int NST = 3;
    constexpr int LPR = KCH / 8;                       // 16B lines per row

    extern __shared__ char smem[];
    const uint32_t sb = smem_u32(smem);
    const int tid = threadIdx.x;
    const int lid = tid & 31;
    const int warp_m = (tid >> 5) & 3;   // 4 M-warps
    const int warp_n = tid >> 7;         // 2 N-warps
    const int m0 = blockIdx.y * 128, n0 = blockIdx.x * 256;

    float acc[2][8][4];
#pragma unroll
    for (int mt = 0; mt < 2; mt++)
#pragma unroll
        for (int nt = 0; nt < 8; nt++)
#pragma unroll
            for (int j = 0; j < 4; j++) acc[mt][nt][j] = 0.0f;

    const int nch = K / KCH;

    auto load_chunk = [&](int ch) {
        const int k0 = ch * KCH;
        const uint32_t base = sb + (ch % NST) * STAGE;
#pragma unroll
        for (int i = 0; i < (128 * LPR) / 512; i++) {   // A lines
            int idx = i * 512 + tid;
            int row = idx / LPR, c4 = idx % LPR;
            uint32_t so = (uint32_t)(row * LT + c4 * 8) * 2;
            size_t ga = (size_t)(m0 + row) * lda + k0 + c4 * 8;
            cp16(base + SAHI + so, Ahi + ga);
            if (PASSES == 3) cp16(base + SALO + so, Alo + ga);
        }
#pragma unroll
        for (int i = 0; i < (256 * LPR) / 512; i++) {   // B lines
            int idx = i * 512 + tid;
            int row = idx / LPR, c4 = idx % LPR;
            uint32_t so = (uint32_t)(row * LT + c4 * 8) * 2;
            size_t gb = (size_t)(n0 + row) * ldb + k0 + c4 * 8;
            cp16(base + SBHI + so, Bhi + gb);
            if (PASSES == 3) cp16(base + SBLO + so, Blo + gb);
        }
    };

    // prologue: NST-1 chunks in flight
#pragma unroll
    for (int i = 0; i < NST - 1; i++) {
        if (i < nch) load_chunk(i);
        CP_COMMIT();
    }

    for (int ch = 0; ch < nch; ch++) {
        asm volatile("cp.async.wait_group %0;" :: "n"(NST - 2) : "memory");
        __syncthreads();
        if (ch + NST - 1 < nch) load_chunk(ch + NST - 1);
        CP_COMMIT();

        const uint32_t base = sb + (ch % NST) * STAGE;
        const uint32_t sA_hi = base + SAHI, sA_lo = base + SALO;
        const uint32_t sB_hi = base + SBHI, sB_lo = base + SBLO;

#pragma unroll
        for (int ks = 0; ks < KCH; ks += 16) {
            const int col = ks + ((lid >> 4) << 3);
            const uint32_t a_off = (uint32_t)((warp_m * 32 + (lid & 15)) * LT + col) * 2;
            const uint32_t b_off = (uint32_t)((warp_n * 64 + (lid & 15)) * LT + col) * 2;

            uint32_t Ah[2][4], Bf[4][4];
            ldsm_x4(Ah[0], sA_hi + a_off);
            ldsm_x4(Ah[1], sA_hi + a_off + 16 * LT * 2);
#pragma unroll
            for (int p = 0; p < 4; p++) ldsm_x4(Bf[p], sB_hi + b_off + p * 16 * LT * 2);

            // pass 1: hi * hi
#pragma unroll
            for (int mt = 0; mt < 2; mt++)
#pragma unroll
                for (int nt = 0; nt < 8; nt++)
                    mma_f16(acc[mt][nt], Ah[mt], Bf[nt >> 1][nt & 1], Bf[nt >> 1][(nt & 1) + 2]);

            if (PASSES == 3) {
                // pass 2: lo * hi
                uint32_t Al[2][4];
                ldsm_x4(Al[0], sA_lo + a_off);
                ldsm_x4(Al[1], sA_lo + a_off + 16 * LT * 2);
#pragma unroll
                for (int mt = 0; mt < 2; mt++)
#pragma unroll
                    for (int nt = 0; nt < 8; nt++)
                        mma_f16(acc[mt][nt], Al[mt], Bf[nt >> 1][nt & 1], Bf[nt >> 1][(nt & 1) + 2]);
                // pass 3: hi * lo
#pragma unroll
                for (int p = 0; p < 4; p++) ldsm_x4(Bf[p], sB_lo + b_off + p * 16 * LT * 2);
#pragma unroll
                for (int mt = 0; mt < 2; mt++)
#pragma unroll
                    for (int nt = 0; nt < 8; nt++)
                        mma_f16(acc[mt][nt], Ah[mt], Bf[nt >> 1][nt & 1], Bf[nt >> 1][(nt & 1) + 2]);
            }
        }
        __syncthreads();
    }

    // epilogue
#pragma unroll
    for (int mt = 0; mt < 2; mt++) {
        const int row = m0 + warp_m * 32 + mt * 16 + (lid >> 2);
#pragma unroll
        for (int nt = 0; nt < 8; nt++) {
            const int colx = n0 + warp_n * 64 + nt * 8 + (lid & 3) * 2;
            if (OUT_HALF) {
                __half2 v0, v1;
                v0.x = __float2half_rn(acc[mt][nt][0]);
                v0.y = __float2half_rn(acc[mt][nt][1]);
                v1.x = __float2half_rn(acc[mt][nt][2]);
                v1.y = __float2half_rn(acc[mt][nt][3]);
                *(__half2*)(Ch + (size_t)row * ldc + colx)       = v0;
                *(__half2*)(Ch + (size_t)(row + 8) * ldc + colx) = v1;
            } else {
                *(float2*)(C + (size_t)row * ldc + colx) =
                    make_float2(acc[mt][nt][0], acc[mt][nt][1]);
                *(float2*)(C + (size_t)(row + 8) * ldc + colx) =
                    make_float2(acc[mt][nt][2], acc[mt][nt][3]);
            }
        }
    }
}

// single-pass fp16 GEMM, fp32 out
__global__ void __launch_bounds__(512, 1) k_gemm(
    const f16* __restrict__ A, const f16* __restrict__ B,
    float* __restrict__ C, int K, int lda, int ldb, int ldc) {
    gemm_body<1, false>(A, nullptr, B, nullptr, C, nullptr, K, lda, ldb, ldc);
}

// causal QK: 3-pass fp16 split (exact-ish scores), skip upper-triangle tiles
__global__ void __launch_bounds__(512, 1) k_qk() {
    if (2 * blockIdx.x > blockIdx.y) return;
    int bh = blockIdx.z;
    int b = bh >> 3, h = bh & 7, kv = h >> 1;
    gemm_body<3, false>(s_q_hi + (size_t)b * SS * QC + h * HD,
                        s_q_lo + (size_t)b * SS * QC + h * HD,
                        s_k_hi + (size_t)b * SS * KC + kv * HD,
                        s_k_lo + (size_t)b * SS * KC + kv * HD,
                        g_sc + (size_t)bh * SS * SS, nullptr,
                        HD, QC, KC, SS);
}

// PV: single-pass fp16, causal K-limit, fp16 out (o)
__global__ void __launch_bounds__(512, 1) k_pv() {
    int bh = blockIdx.z;
    int b = bh >> 3, h = bh & 7, kv = h >> 1;
    int klim = (blockIdx.y + 1) * 128;
    if (klim > SS) klim = SS;
    gemm_body<1, true>(s_p + (size_t)bh * SS * SS, nullptr,
                       s_vt + (size_t)(b * NKV + kv) * HD * SS, nullptr,
                       nullptr, s_o + (size_t)b * SS * QC + h * HD,
                       klim, SS, SS, QC);
}

// ---------------- transpose / elementwise ----------------
// transpose: fp32 [R,C] -> fp16 [C,R]
__global__ void __launch_bounds__(256) k_t16(const float* __restrict__ in,
                                             f16* __restrict__ o, int R, int C) {
    __shared__ float t[32][33];
    int c0 = blockIdx.x * 32, r0 = blockIdx.y * 32;
    int tx = threadIdx.x & 31, ty = threadIdx.x >> 5;
#pragma unroll
    for (int i = 0; i < 4; i++)
        t[ty + i * 8][tx] = in[(size_t)(r0 + ty + i * 8) * C + c0 + tx];
    __syncthreads();
#pragma unroll
    for (int i = 0; i < 4; i++)
        o[(size_t)(c0 + ty + i * 8) * R + r0 + tx] = __float2half_rn(t[tx][ty + i * 8]);
}

// rmsnorm -> fp16
__global__ void __launch_bounds__(256) k_rms16(const float* __restrict__ x,
                                               const float* __restrict__ g,
                                               f16* __restrict__ o) {
    int row = blockIdx.x;
    const float* xr = x + (size_t)row * HH;
    float s = 0.0f;
    for (int i = threadIdx.x; i < HH; i += 256) { float v = xr[i]; s = fmaf(v, v, s); }
    __shared__ float red[256];
    red[threadIdx.x] = s;
    __syncthreads();
    for (int off = 128; off > 0; off >>= 1) {
        if (threadIdx.x < off) red[threadIdx.x] += red[threadIdx.x + off];
        __syncthreads();
    }
    float rstd = rsqrtf(red[0] * (1.0f / HH) + RMS_EPS);
    size_t base = (size_t)row * HH;
    for (int i = threadIdx.x; i < HH; i += 256)
        o[base + i] = __float2half_rn(xr[i] * rstd * (1.0f + g[i]));
}

// out = res + rmsnorm(y, g)  (fp32)
__global__ void __launch_bounds__(256) k_add_rms(const float* __restrict__ res,
                                                 const float* __restrict__ y,
                                                 const float* __restrict__ g,
                                                 float* __restrict__ out) {
    int row = blockIdx.x;
    const float* yr = y + (size_t)row * HH;
    float s = 0.0f;
    for (int i = threadIdx.x; i < HH; i += 256) { float v = yr[i]; s = fmaf(v, v, s); }
    __shared__ float red[256];
    red[threadIdx.x] = s;
    __syncthreads();
    for (int off = 128; off > 0; off >>= 1) {
        if (threadIdx.x < off) red[threadIdx.x] += red[threadIdx.x + off];
        __syncthreads();
    }
    float rstd = rsqrtf(red[0] * (1.0f / HH) + RMS_EPS);
    const float* rr = res + (size_t)row * HH;
    float* orow = out + (size_t)row * HH;
    for (int i = threadIdx.x; i < HH; i += 256)
        orow[i] = rr[i] + yr[i] * rstd * (1.0f + g[i]);
}

// RoPE on fp32 q/k -> fp16 hi/lo split buffers
__global__ void __launch_bounds__(256) k_rope_split() {
    int idx = blockIdx.x * 256 + threadIdx.x;            // < MROWS*12*128
    int j = idx & 127;
    int hd = (idx >> 7) % 12;
    int row = idx / (12 * 128);
    int pos = row & (SS - 1);
    float inv = __powf(10000.0f, -(float)(2 * j) * (1.0f / HD));
    float fr = (float)pos * inv;
    float sn, cs;
    sincosf(fr, &sn, &cs);
    const float* base;
    f16 *ohi, *olo;
    size_t off;
    if (hd < 8) {
        off = (size_t)row * QC + hd * HD;
        base = g_q + off; ohi = s_q_hi + off; olo = s_q_lo + off;
    } else {
        off = (size_t)row * KC + (hd - 8) * HD;
        base = g_k + off; ohi = s_k_hi + off; olo = s_k_lo + off;
    }
    float v0 = base[j], v1 = base[j + 128];
    split2h(v0 * cs - v1 * sn, ohi + j, olo + j);
    split2h(v1 * cs + v0 * sn, ohi + j + 128, olo + j + 128);
}

// V: fp32 [B,S,NKV,HD] -> fp16 transposed [B*NKV, HD, S]
__global__ void __launch_bounds__(256) k_vtrans() {
    __shared__ float t[32][33];
    int bkv = blockIdx.z;
    int b = bkv >> 2, kv = bkv & 3;
    int d0 = blockIdx.x * 32, s0 = blockIdx.y * 32;
    int tx = threadIdx.x & 31, ty = threadIdx.x >> 5;
#pragma unroll
    for (int i = 0; i < 4; i++)
        t[ty + i * 8][tx] = g_v[(size_t)(b * SS + s0 + ty + i * 8) * KC + kv * HD + d0 + tx];
    __syncthreads();
#pragma unroll
    for (int i = 0; i < 4; i++) {
        size_t o = (size_t)bkv * HD * SS + (size_t)(d0 + ty + i * 8) * SS + s0 + tx;
        s_vt[o] = __float2half_rn(t[tx][ty + i * 8]);
    }
}

// softmax (softcap + causal): only j <= qi read; zero-fill to 128-boundary; fp16 out
__global__ void __launch_bounds__(256) k_softmax() {
    int r = blockIdx.x;                 // bh*SS + qi
    int qi = r & (SS - 1);
    int nr = ((qi >> 7) + 1) << 7;
    const float* row = g_sc + (size_t)r * SS;
    int t = threadIdx.x;
    float vals[8];
    float mx = -1e30f;
    int it = 0;
    for (int j = t; j < nr; j += 256, it++) {
        float s = -1e30f;
        if (j <= qi) {
            s = row[j] * ATT_SCALE;
            s = SOFTCAP * tanhf(s * (1.0f / SOFTCAP));
            mx = fmaxf(mx, s);
        }
        vals[it] = s;
    }
    __shared__ float red[256];
    red[t] = mx;
    __syncthreads();
    for (int off = 128; off > 0; off >>= 1) {
        if (t < off) red[t] = fmaxf(red[t], red[t + off]);
        __syncthreads();
    }
    mx = red[0];
    __syncthreads();
    float sum = 0.0f;
    it = 0;
    for (int j = t; j < nr; j += 256, it++) {
        float e = (vals[it] > -1e29f) ? __expf(vals[it] - mx) : 0.0f;
        vals[it] = e;
        sum += e;
    }
    red[t] = sum;
    __syncthreads();
    for (int off = 128; off > 0; off >>= 1) {
        if (t < off) red[t] += red[t + off];
        __syncthreads();
    }
    float inv = 1.0f / red[0];
    size_t base = (size_t)r * SS;
    it = 0;
    for (int j = t; j < nr; j += 256, it++)
        s_p[base + j] = __float2half_rn(vals[it] * inv);
}

// GeGLU: act = gelu_tanh(gate) * up -> fp16
__global__ void __launch_bounds__(256) k_geglu() {
    size_t i = (size_t)blockIdx.x * 256 + threadIdx.x;
    float x = g_gate[i];
    float u = g_up[i];
    const float c0 = 0.7978845608028654f;
    float inner = c0 * fmaf(0.044715f * x * x, x, x);
    float act = 0.5f * x * (1.0f + tanhf(inner)) * u;
    s_a[i] = __float2half_rn(act);
}

// ---------------- launch ----------------
extern "C" void kernel_launch(void* const* d_in, const int* in_sizes, int n_in,
                              void* d_out, int out_size) {
    const float* x      = (const float*)d_in[0];
    // d_in[1] = mask (pure causal; applied analytically)
    const float* wq     = (const float*)d_in[2];
    const float* wk     = (const float*)d_in[3];
    const float* wv     = (const float*)d_in[4];
    const float* wo     = (const float*)d_in[5];
    const float* w_gate = (const float*)d_in[6];
    const float* w_up   = (const float*)d_in[7];
    const float* w_down = (const float*)d_in[8];
    const float* gin    = (const float*)d_in[9];
    const float* gpa    = (const float*)d_in[10];
    const float* gpf    = (const float*)d_in[11];
    const float* gpff   = (const float*)d_in[12];
    float* out = (float*)d_out;

    cudaFuncSetAttribute(k_gemm, cudaFuncAttributeMaxDynamicSharedMemorySize, SMEM_G1);
    cudaFuncSetAttribute(k_pv,   cudaFuncAttributeMaxDynamicSharedMemorySize, SMEM_G1);
    cudaFuncSetAttribute(k_qk,   cudaFuncAttributeMaxDynamicSharedMemorySize, SMEM_G3);

#define SYM(p, s) void* p; cudaGetSymbolAddress(&p, s)
    SYM(p_h, s_h);
    SYM(p_q, g_q);  SYM(p_k, g_k);  SYM(p_v, g_v);
    SYM(p_o, s_o);
    SYM(p_attn, g_attn); SYM(p_h2, g_h2); SYM(p_f, s_f);
    SYM(p_gate, g_gate); SYM(p_up, g_up); SYM(p_a, s_a);
    SYM(p_mlp, g_mlp);
    SYM(p_wq, w_qt); SYM(p_wk, w_kt); SYM(p_wv, w_vt); SYM(p_wo, w_ot);
    SYM(p_wg, w_gt); SYM(p_wu, w_ut); SYM(p_wd, w_dt);
#undef SYM

    // launches 0-4 so launch #5 = Q-projection GEMM (ncu -s 5 -c 1 target)
    k_t16<<<dim3(QC / 32, HH / 32), 256>>>(wq, (f16*)p_wq, HH, QC);   // 0
    k_t16<<<dim3(KC / 32, HH / 32), 256>>>(wk, (f16*)p_wk, HH, KC);   // 1
    k_t16<<<dim3(KC / 32, HH / 32), 256>>>(wv, (f16*)p_wv, HH, KC);   // 2
    k_t16<<<dim3(HH / 32, QC / 32), 256>>>(wo, (f16*)p_wo, QC, HH);   // 3
    k_rms16<<<MROWS, 256>>>(x, gin, (f16*)p_h);                       // 4

    // 5: Q projection (ncu target), then K/V
    k_gemm<<<dim3(QC / 256, MROWS / 128), 512, SMEM_G1>>>(
        (f16*)p_h, (f16*)p_wq, (float*)p_q, HH, HH, HH, QC);
    k_gemm<<<dim3(KC / 256, MROWS / 128), 512, SMEM_G1>>>(
        (f16*)p_h, (f16*)p_wk, (float*)p_k, HH, HH, HH, KC);
    k_gemm<<<dim3(KC / 256, MROWS / 128), 512, SMEM_G1>>>(
        (f16*)p_h, (f16*)p_wv, (float*)p_v, HH, HH, HH, KC);

    // remaining weight transposes
    k_t16<<<dim3(FF / 32, HH / 32), 256>>>(w_gate, (f16*)p_wg, HH, FF);
    k_t16<<<dim3(FF / 32, HH / 32), 256>>>(w_up,   (f16*)p_wu, HH, FF);
    k_t16<<<dim3(HH / 32, FF / 32), 256>>>(w_down, (f16*)p_wd, FF, HH);

    // RoPE -> q/k fp16 hi/lo; V transpose -> fp16
    k_rope_split<<<(MROWS * 12 * 128) / 256, 256>>>();
    k_vtrans<<<dim3(HD / 32, SS / 32, BB * NKV), 256>>>();

    // scores = q @ k^T (3-pass, causal tiles only)
    k_qk<<<dim3(SS / 256, SS / 128, BB * NH), 512, SMEM_G3>>>();

    // softcap + causal + softmax -> p fp16
    k_softmax<<<BB * NH * SS, 256>>>();

    // o = p @ v (causal K-limit, fp16 out)
    k_pv<<<dim3(HD / 256, SS / 128, BB * NH), 512, SMEM_G1>>>();

    // attn_out = o @ wo
    k_gemm<<<dim3(HH / 256, MROWS / 128), 512, SMEM_G1>>>(
        (f16*)p_o, (f16*)p_wo, (float*)p_attn, QC, QC, QC, HH);

    // h2 = x + rmsnorm(attn); f = rmsnorm(h2) -> fp16
    k_add_rms<<<MROWS, 256>>>(x, (float*)p_attn, gpa, (float*)p_h2);
    k_rms16<<<MROWS, 256>>>((float*)p_h2, gpf, (f16*)p_f);

    // gate/up
    k_gemm<<<dim3(FF / 256, MROWS / 128), 512, SMEM_G1>>>(
        (f16*)p_f, (f16*)p_wg, (float*)p_gate, HH, HH, HH, FF);
    k_gemm<<<dim3(FF / 256, MROWS / 128), 512, SMEM_G1>>>(
        (f16*)p_f, (f16*)p_wu, (float*)p_up, HH, HH, HH, FF);

    // GeGLU -> fp16
    k_geglu<<<(int)(((size_t)MROWS * FF) / 256), 256>>>();

    // mlp = act @ w_down
    k_gemm<<<dim3(HH / 256, MROWS / 128), 512, SMEM_G1>>>(
        (f16*)p_a, (f16*)p_wd, (float*)p_mlp, FF, FF, FF, HH);

    // out = h2 + rmsnorm(mlp)
    k_add_rms<<<MROWS, 256>>>((float*)p_h2, (float*)p_mlp, gpff, out);
}

// round 15
// speedup vs baseline: 1.1378x; 1.0368x over previous
#include <cuda_runtime.h>
#include <cuda_fp16.h>
#include <math.h>
#include <stdint.h>

// ---------------- problem constants ----------------
#define BB 2
#define SS 2048
#define HH 2304
#define NH 8
#define NKV 4
#define HD 256
#define FF 9216
#define MROWS (BB * SS)          // 4096
#define QC (NH * HD)             // 2048
#define KC (NKV * HD)            // 1024
#define QKVC (QC + 2 * KC)       // 4096
#define SOFTCAP 50.0f
#define ATT_SCALE 0.0625f
#define RMS_EPS 1e-6f

typedef __half f16;

// ---------------- scratch (device globals; no allocations) ----------------
#define DEVBUF __device__ __align__(256)
DEVBUF f16   s_h   [(size_t)MROWS * HH];
DEVBUF float g_qkv [(size_t)MROWS * QKVC];
DEVBUF f16   s_q_hi[(size_t)MROWS * QC];  DEVBUF f16 s_q_lo[(size_t)MROWS * QC];
DEVBUF f16   s_k_hi[(size_t)MROWS * KC];  DEVBUF f16 s_k_lo[(size_t)MROWS * KC];
DEVBUF f16   s_vt  [(size_t)MROWS * KC];
DEVBUF float g_sc  [(size_t)BB * NH * SS * SS];
DEVBUF f16   s_p   [(size_t)BB * NH * SS * SS];
DEVBUF f16   s_o   [(size_t)MROWS * QC];
DEVBUF float g_attn[(size_t)MROWS * HH];
DEVBUF float g_h2  [(size_t)MROWS * HH];
DEVBUF f16   s_f   [(size_t)MROWS * HH];
DEVBUF f16   s_a   [(size_t)MROWS * FF];
DEVBUF float g_mlp [(size_t)MROWS * HH];
// transposed weights ([N,K] K-major, fp16)
DEVBUF f16 w_qkv[(size_t)QKVC * HH];          // rows: 0..2047 q, 2048..3071 k, 3072..4095 v
DEVBUF f16 w_ot [(size_t)HH * QC];
DEVBUF f16 w_gu [(size_t)(2 * FF) * HH];      // per 256-row block: 128 gate rows + 128 up rows
DEVBUF f16 w_dt [(size_t)HH * FF];

// ---------------- PTX helpers ----------------
__device__ __forceinline__ uint32_t smem_u32(const void* p) {
    uint32_t a;
    asm("{ .reg .u64 t; cvta.to.shared.u64 t, %1; cvt.u32.u64 %0, t; }" : "=r"(a) : "l"(p));
    return a;
}
__device__ __forceinline__ void cp16(uint32_t saddr, const void* g) {
    asm volatile("cp.async.cg.shared.global [%0], [%1], 16;" :: "r"(saddr), "l"(g));
}
#define CP_COMMIT() asm volatile("cp.async.commit_group;" ::: "memory")

__device__ __forceinline__ void ldsm_x4(uint32_t (&r)[4], uint32_t addr) {
    asm volatile("ldmatrix.sync.aligned.m8n8.x4.shared.b16 {%0,%1,%2,%3}, [%4];"
                 : "=r"(r[0]), "=r"(r[1]), "=r"(r[2]), "=r"(r[3]) : "r"(addr));
}
__device__ __forceinline__ void mma_f16(float (&c)[4], const uint32_t (&a)[4],
                                        uint32_t b0, uint32_t b1) {
    asm volatile(
        "mma.sync.aligned.m16n8k16.row.col.f32.f16.f16.f32 "
        "{%0,%1,%2,%3}, {%4,%5,%6,%7}, {%8,%9}, {%0,%1,%2,%3};"
        : "+f"(c[0]), "+f"(c[1]), "+f"(c[2]), "+f"(c[3])
        : "r"(a[0]), "r"(a[1]), "r"(a[2]), "r"(a[3]), "r"(b0), "r"(b1));
}

__device__ __forceinline__ void split2h(float v, f16* hi, f16* lo) {
    f16 h = __float2half_rn(v);
    *hi = h;
    *lo = __float2half_rn(v - __half2float(h));
}

// ---------------- GEMM config ----------------
// CTA tile 128(M) x 256(N), 512 threads (16 warps, 4(M) x 2(N)), warp tile 32x64.
// PASSES=1: K-chunk 64, LDS_T=72, 3 stages.  PASSES=3: K-chunk 32, LDS_T=40, 3 stages.
#define LT1    72
#define TA1_B  (128 * LT1 * 2)            // 18432 B
#define TB1_B  (256 * LT1 * 2)            // 36864 B
#define SMEM_G1 (3 * (TA1_B + TB1_B))     // 165888 B

#define LT3    40
#define TA3_B  (128 * LT3 * 2)            // 10240 B
#define TB3_B  (256 * LT3 * 2)            // 20480 B
#define SMEM_G3 (3 * 2 * (TA3_B + TB3_B)) // 184320 B

// OUTMODE: 0 = fp32 C; 1 = fp16 Ch; 2 = fused GeGLU (256-col tile = 128 gate + 128 up
//          for ff cols [bx*128, bx*128+128); writes fp16 act to Ch with row stride FF).
template<int PASSES, int OUTMODE>
__device__ __forceinline__ void gemm_body(
    const f16* __restrict__ Ahi, const f16* __restrict__ Alo,
    const f16* __restrict__ Bhi, const f16* __restrict__ Blo,
    float* __restrict__ C, f16* __restrict__ Ch,
    int K, int lda, int ldb, int ldc) {
    constexpr int KCH  = (PASSES == 3) ? 32 : 64;
    constexpr int LT   = (PASSES == 3) ? LT3 : LT1;
    constexpr int TA_B = 128 * LT * 2;
    constexpr int TB_B = 256 * LT * 2;
    constexpr int SAHI = 0;
    constexpr int SALO = (PASSES == 3) ? TA_B : 0;
    constexpr int SBHI = (PASSES == 3) ? 2 * TA_B : TA_B;
    constexpr int SBLO = (PASSES == 3) ? 2 * TA_B + TB_B : 0;
    constexpr int STAGE = (PASSES == 3) ? 2 * (TA_B + TB_B) : (TA_B + TB_B);
    constexpr int NST = 3;
    constexpr int LPR = KCH / 8;

    extern __shared__ char smem[];
    const uint32_t sb = smem_u32(smem);
    const int tid = threadIdx.x;
    const int lid = tid & 31;
    const int warp_m = (tid >> 5) & 3;
    const int warp_n = tid >> 7;
    const int m0 = blockIdx.y * 128, n0 = blockIdx.x * 256;

    float acc[2][8][4];
#pragma unroll
    for (int mt = 0; mt < 2; mt++)
#pragma unroll
        for (int nt = 0; nt < 8; nt++)
#pragma unroll
            for (int j = 0; j < 4; j++) acc[mt][nt][j] = 0.0f;

    const int nch = K / KCH;

    auto load_chunk = [&](int ch) {
        const int k0 = ch * KCH;
        const uint32_t base = sb + (ch % NST) * STAGE;
#pragma unroll
        for (int i = 0; i < (128 * LPR) / 512; i++) {
            int idx = i * 512 + tid;
            int row = idx / LPR, c4 = idx % LPR;
            uint32_t so = (uint32_t)(row * LT + c4 * 8) * 2;
            size_t ga = (size_t)(m0 + row) * lda + k0 + c4 * 8;
            cp16(base + SAHI + so, Ahi + ga);
            if (PASSES == 3) cp16(base + SALO + so, Alo + ga);
        }
#pragma unroll
        for (int i = 0; i < (256 * LPR) / 512; i++) {
            int idx = i * 512 + tid;
            int row = idx / LPR, c4 = idx % LPR;
            uint32_t so = (uint32_t)(row * LT + c4 * 8) * 2;
            size_t gb = (size_t)(n0 + row) * ldb + k0 + c4 * 8;
            cp16(base + SBHI + so, Bhi + gb);
            if (PASSES == 3) cp16(base + SBLO + so, Blo + gb);
        }
    };

#pragma unroll
    for (int i = 0; i < NST - 1; i++) {
        if (i < nch) load_chunk(i);
        CP_COMMIT();
    }

    for (int ch = 0; ch < nch; ch++) {
        asm volatile("cp.async.wait_group %0;" :: "n"(NST - 2) : "memory");
        __syncthreads();
        if (ch + NST - 1 < nch) load_chunk(ch + NST - 1);
        CP_COMMIT();

        const uint32_t base = sb + (ch % NST) * STAGE;
        const uint32_t sA_hi = base + SAHI, sA_lo = base + SALO;
        const uint32_t sB_hi = base + SBHI, sB_lo = base + SBLO;

#pragma unroll
        for (int ks = 0; ks < KCH; ks += 16) {
            const int col = ks + ((lid >> 4) << 3);
            const uint32_t a_off = (uint32_t)((warp_m * 32 + (lid & 15)) * LT + col) * 2;
            const uint32_t b_off = (uint32_t)((warp_n * 64 + (lid & 15)) * LT + col) * 2;

            uint32_t Ah[2][4], Bf[4][4];
            ldsm_x4(Ah[0], sA_hi + a_off);
            ldsm_x4(Ah[1], sA_hi + a_off + 16 * LT * 2);
#pragma unroll
            for (int p = 0; p < 4; p++) ldsm_x4(Bf[p], sB_hi + b_off + p * 16 * LT * 2);

            // pass 1: hi * hi
#pragma unroll
            for (int mt = 0; mt < 2; mt++)
#pragma unroll
                for (int nt = 0; nt < 8; nt++)
                    mma_f16(acc[mt][nt], Ah[mt], Bf[nt >> 1][nt & 1], Bf[nt >> 1][(nt & 1) + 2]);

            if (PASSES == 3) {
                // pass 2: lo * hi
                uint32_t Al[2][4];
                ldsm_x4(Al[0], sA_lo + a_off);
                ldsm_x4(Al[1], sA_lo + a_off + 16 * LT * 2);
#pragma unroll
                for (int mt = 0; mt < 2; mt++)
#pragma unroll
                    for (int nt = 0; nt < 8; nt++)
                        mma_f16(acc[mt][nt], Al[mt], Bf[nt >> 1][nt & 1], Bf[nt >> 1][(nt & 1) + 2]);
                // pass 3: hi * lo
#pragma unroll
                for (int p = 0; p < 4; p++) ldsm_x4(Bf[p], sB_lo + b_off + p * 16 * LT * 2);
#pragma unroll
                for (int mt = 0; mt < 2; mt++)
#pragma unroll
                    for (int nt = 0; nt < 8; nt++)
                        mma_f16(acc[mt][nt], Ah[mt], Bf[nt >> 1][nt & 1], Bf[nt >> 1][(nt & 1) + 2]);
            }
        }
        __syncthreads();
    }

    if (OUTMODE == 2) {
        // fused GeGLU epilogue: stage acc to SMEM, combine gate (cols 0-127) with up (cols 128-255)
        float* sf = (float*)smem;
#pragma unroll
        for (int mt = 0; mt < 2; mt++) {
            const int r = warp_m * 32 + mt * 16 + (lid >> 2);
#pragma unroll
            for (int nt = 0; nt < 8; nt++) {
                const int c = warp_n * 64 + nt * 8 + (lid & 3) * 2;
                sf[(size_t)r * 260 + c]           = acc[mt][nt][0];
                sf[(size_t)r * 260 + c + 1]       = acc[mt][nt][1];
                sf[(size_t)(r + 8) * 260 + c]     = acc[mt][nt][2];
                sf[(size_t)(r + 8) * 260 + c + 1] = acc[mt][nt][3];
            }
        }
        __syncthreads();
        const int ffbase = blockIdx.x * 128;
        const float c0 = 0.7978845608028654f;
#pragma unroll 4
        for (int i = tid; i < 128 * 128; i += 512) {
            int r = i >> 7, j = i & 127;
            float x = sf[r * 260 + j];
            float u = sf[r * 260 + j + 128];
            float inner = c0 * fmaf(0.044715f * x * x, x, x);
            float act = 0.5f * x * (1.0f + tanhf(inner)) * u;
            Ch[(size_t)(m0 + r) * FF + ffbase + j] = __float2half_rn(act);
        }
        return;
    }

#pragma unroll
    for (int mt = 0; mt < 2; mt++) {
        const int row = m0 + warp_m * 32 + mt * 16 + (lid >> 2);
#pragma unroll
        for (int nt = 0; nt < 8; nt++) {
            const int colx = n0 + warp_n * 64 + nt * 8 + (lid & 3) * 2;
            if (OUTMODE == 1) {
                __half2 v0, v1;
                v0.x = __float2half_rn(acc[mt][nt][0]);
                v0.y = __float2half_rn(acc[mt][nt][1]);
                v1.x = __float2half_rn(acc[mt][nt][2]);
                v1.y = __float2half_rn(acc[mt][nt][3]);
                *(__half2*)(Ch + (size_t)row * ldc + colx)       = v0;
                *(__half2*)(Ch + (size_t)(row + 8) * ldc + colx) = v1;
            } else {
                *(float2*)(C + (size_t)row * ldc + colx) =
                    make_float2(acc[mt][nt][0], acc[mt][nt][1]);
                *(float2*)(C + (size_t)(row + 8) * ldc + colx) =
                    make_float2(acc[mt][nt][2], acc[mt][nt][3]);
            }
        }
    }
}

// single-pass fp16 GEMM, fp32 out
__global__ void __launch_bounds__(512, 1) k_gemm(
    const f16* __restrict__ A, const f16* __restrict__ B,
    float* __restrict__ C, int K, int lda, int ldb, int ldc) {
    gemm_body<1, 0>(A, nullptr, B, nullptr, C, nullptr, K, lda, ldb, ldc);
}

// merged gate+up GEMM with fused GeGLU -> s_a fp16
__global__ void __launch_bounds__(512, 1) k_gu() {
    gemm_body<1, 2>(s_f, nullptr, w_gu, nullptr, nullptr, s_a, HH, HH, HH, FF);
}

// causal QK: 3-pass fp16 split, skip upper-triangle tiles
__global__ void __launch_bounds__(512, 1) k_qk() {
    if (2 * blockIdx.x > blockIdx.y) return;
    int bh = blockIdx.z;
    int b = bh >> 3, h = bh & 7, kv = h >> 1;
    gemm_body<3, 0>(s_q_hi + (size_t)b * SS * QC + h * HD,
                    s_q_lo + (size_t)b * SS * QC + h * HD,
                    s_k_hi + (size_t)b * SS * KC + kv * HD,
                    s_k_lo + (size_t)b * SS * KC + kv * HD,
                    g_sc + (size_t)bh * SS * SS, nullptr,
                    HD, QC, KC, SS);
}

// PV: single-pass fp16, causal K-limit, fp16 out (o)
__global__ void __launch_bounds__(512, 1) k_pv() {
    int bh = blockIdx.z;
    int b = bh >> 3, h = bh & 7, kv = h >> 1;
    int klim = (blockIdx.y + 1) * 128;
    if (klim > SS) klim = SS;
    gemm_body<1, 1>(s_p + (size_t)bh * SS * SS, nullptr,
                    s_vt + (size_t)(b * NKV + kv) * HD * SS, nullptr,
                    nullptr, s_o + (size_t)b * SS * QC + h * HD,
                    klim, SS, SS, QC);
}

// ---------------- transpose / elementwise ----------------
// transpose: fp32 [R,C] -> fp16 [C,R]
__global__ void __launch_bounds__(256) k_t16(const float* __restrict__ in,
                                             f16* __restrict__ o, int R, int C) {
    __shared__ float t[32][33];
    int c0 = blockIdx.x * 32, r0 = blockIdx.y * 32;
    int tx = threadIdx.x & 31, ty = threadIdx.x >> 5;
#pragma unroll
    for (int i = 0; i < 4; i++)
        t[ty + i * 8][tx] = in[(size_t)(r0 + ty + i * 8) * C + c0 + tx];
    __syncthreads();
#pragma unroll
    for (int i = 0; i < 4; i++)
        o[(size_t)(c0 + ty + i * 8) * R + r0 + tx] = __float2half_rn(t[tx][ty + i * 8]);
}

// transpose gate/up fp32 [HH, FF] -> interleaved w_gu fp16: block t (256 rows) =
// gate ff-cols [t*128,(t+1)*128) then up same. blockIdx.z: 0=gate, 1=up.
__global__ void __launch_bounds__(256) k_t16gu(const float* __restrict__ gate,
                                               const float* __restrict__ up) {
    __shared__ float t[32][33];
    const float* in = blockIdx.z ? up : gate;
    int c0 = blockIdx.x * 32, r0 = blockIdx.y * 32;   // c = ff index, r = HH index
    int tx = threadIdx.x & 31, ty = threadIdx.x >> 5;
#pragma unroll
    for (int i = 0; i < 4; i++)
        t[ty + i * 8][tx] = in[(size_t)(r0 + ty + i * 8) * FF + c0 + tx];
    __syncthreads();
#pragma unroll
    for (int i = 0; i < 4; i++) {
        int cf = c0 + ty + i * 8;                     // ff index
        int orow = (cf >> 7) * 256 + (cf & 127) + (blockIdx.z ? 128 : 0);
        w_gu[(size_t)orow * HH + r0 + tx] = __float2half_rn(t[tx][ty + i * 8]);
    }
}

// rmsnorm -> fp16
__global__ void __launch_bounds__(256) k_rms16(const float* __restrict__ x,
                                               const float* __restrict__ g,
                                               f16* __restrict__ o) {
    int row = blockIdx.x;
    const float* xr = x + (size_t)row * HH;
    float s = 0.0f;
    for (int i = threadIdx.x; i < HH; i += 256) { float v = xr[i]; s = fmaf(v, v, s); }
    __shared__ float red[256];
    red[threadIdx.x] = s;
    __syncthreads();
    for (int off = 128; off > 0; off >>= 1) {
        if (threadIdx.x < off) red[threadIdx.x] += red[threadIdx.x + off];
        __syncthreads();
    }
    float rstd = rsqrtf(red[0] * (1.0f / HH) + RMS_EPS);
    size_t base = (size_t)row * HH;
    for (int i = threadIdx.x; i < HH; i += 256)
        o[base + i] = __float2half_rn(xr[i] * rstd * (1.0f + g[i]));
}

// out = res + rmsnorm(y, g)  (fp32)
__global__ void __launch_bounds__(256) k_add_rms(const float* __restrict__ res,
                                                 const float* __restrict__ y,
                                                 const float* __restrict__ g,
                                                 float* __restrict__ out) {
    int row = blockIdx.x;
    const float* yr = y + (size_t)row * HH;
    float s = 0.0f;
    for (int i = threadIdx.x; i < HH; i += 256) { float v = yr[i]; s = fmaf(v, v, s); }
    __shared__ float red[256];
    red[threadIdx.x] = s;
    __syncthreads();
    for (int off = 128; off > 0; off >>= 1) {
        if (threadIdx.x < off) red[threadIdx.x] += red[threadIdx.x + off];
        __syncthreads();
    }
    float rstd = rsqrtf(red[0] * (1.0f / HH) + RMS_EPS);
    const float* rr = res + (size_t)row * HH;
    float* orow = out + (size_t)row * HH;
    for (int i = threadIdx.x; i < HH; i += 256)
        orow[i] = rr[i] + yr[i] * rstd * (1.0f + g[i]);
}

// RoPE on fp32 qkv buffer -> fp16 hi/lo split buffers
__global__ void __launch_bounds__(256) k_rope_split() {
    int idx = blockIdx.x * 256 + threadIdx.x;            // < MROWS*12*128
    int j = idx & 127;
    int hd = (idx >> 7) % 12;
    int row = idx / (12 * 128);
    int pos = row & (SS - 1);
    float inv = __powf(10000.0f, -(float)(2 * j) * (1.0f / HD));
    float fr = (float)pos * inv;
    float sn, cs;
    sincosf(fr, &sn, &cs);
    const float* base;
    f16 *ohi, *olo;
    if (hd < 8) {
        base = g_qkv + (size_t)row * QKVC + hd * HD;
        size_t off = (size_t)row * QC + hd * HD;
        ohi = s_q_hi + off; olo = s_q_lo + off;
    } else {
        base = g_qkv + (size_t)row * QKVC + QC + (hd - 8) * HD;
        size_t off = (size_t)row * KC + (hd - 8) * HD;
        ohi = s_k_hi + off; olo = s_k_lo + off;
    }
    float v0 = base[j], v1 = base[j + 128];
    split2h(v0 * cs - v1 * sn, ohi + j, olo + j);
    split2h(v1 * cs + v0 * sn, ohi + j + 128, olo + j + 128);
}

// V (g_qkv cols 3072..4095): fp32 [B,S,NKV,HD] -> fp16 transposed [B*NKV, HD, S]
__global__ void __launch_bounds__(256) k_vtrans() {
    __shared__ float t[32][33];
    int bkv = blockIdx.z;
    int b = bkv >> 2, kv = bkv & 3;
    int d0 = blockIdx.x * 32, s0 = blockIdx.y * 32;
    int tx = threadIdx.x & 31, ty = threadIdx.x >> 5;
#pragma unroll
    for (int i = 0; i < 4; i++)
        t[ty + i * 8][tx] = g_qkv[(size_t)(b * SS + s0 + ty + i * 8) * QKVC
                                  + QC + KC + kv * HD + d0 + tx];
    __syncthreads();
#pragma unroll
    for (int i = 0; i < 4; i++) {
        size_t o = (size_t)bkv * HD * SS + (size_t)(d0 + ty + i * 8) * SS + s0 + tx;
        s_vt[o] = __float2half_rn(t[tx][ty + i * 8]);
    }
}

// softmax (softcap + causal): only j <= qi read; zero-fill to 128-boundary; fp16 out
__global__ void __launch_bounds__(256) k_softmax() {
    int r = blockIdx.x;                 // bh*SS + qi
    int qi = r & (SS - 1);
    int nr = ((qi >> 7) + 1) << 7;
    const float* row = g_sc + (size_t)r * SS;
    int t = threadIdx.x;
    float vals[8];
    float mx = -1e30f;
    int it = 0;
    for (int j = t; j < nr; j += 256, it++) {
        float s = -1e30f;
        if (j <= qi) {
            s = row[j] * ATT_SCALE;
            s = SOFTCAP * tanhf(s * (1.0f / SOFTCAP));
            mx = fmaxf(mx, s);
        }
        vals[it] = s;
    }
    __shared__ float red[256];
    red[t] = mx;
    __syncthreads();
    for (int off = 128; off > 0; off >>= 1) {
        if (t < off) red[t] = fmaxf(red[t], red[t + off]);
        __syncthreads();
    }
    mx = red[0];
    __syncthreads();
    float sum = 0.0f;
    it = 0;
    for (int j = t; j < nr; j += 256, it++) {
        float e = (vals[it] > -1e29f) ? __expf(vals[it] - mx) : 0.0f;
        vals[it] = e;
        sum += e;
    }
    red[t] = sum;
    __syncthreads();
    for (int off = 128; off > 0; off >>= 1) {
        if (t < off) red[t] += red[t + off];
        __syncthreads();
    }
    float inv = 1.0f / red[0];
    size_t base = (size_t)r * SS;
    it = 0;
    for (int j = t; j < nr; j += 256, it++)
        s_p[base + j] = __float2half_rn(vals[it] * inv);
}

// ---------------- launch ----------------
extern "C" void kernel_launch(void* const* d_in, const int* in_sizes, int n_in,
                              void* d_out, int out_size) {
    const float* x      = (const float*)d_in[0];
    // d_in[1] = mask (pure causal; applied analytically)
    const float* wq     = (const float*)d_in[2];
    const float* wk     = (const float*)d_in[3];
    const float* wv     = (const float*)d_in[4];
    const float* wo     = (const float*)d_in[5];
    const float* w_gate = (const float*)d_in[6];
    const float* w_up   = (const float*)d_in[7];
    const float* w_down = (const float*)d_in[8];
    const float* gin    = (const float*)d_in[9];
    const float* gpa    = (const float*)d_in[10];
    const float* gpf    = (const float*)d_in[11];
    const float* gpff   = (const float*)d_in[12];
    float* out = (float*)d_out;

    cudaFuncSetAttribute(k_gemm, cudaFuncAttributeMaxDynamicSharedMemorySize, SMEM_G1);
    cudaFuncSetAttribute(k_gu,   cudaFuncAttributeMaxDynamicSharedMemorySize, SMEM_G1);
    cudaFuncSetAttribute(k_pv,   cudaFuncAttributeMaxDynamicSharedMemorySize, SMEM_G1);
    cudaFuncSetAttribute(k_qk,   cudaFuncAttributeMaxDynamicSharedMemorySize, SMEM_G3);

#define SYM(p, s) void* p; cudaGetSymbolAddress(&p, s)
    SYM(p_h, s_h);       SYM(p_qkv, g_qkv);   SYM(p_o, s_o);
    SYM(p_attn, g_attn); SYM(p_h2, g_h2);     SYM(p_f, s_f);
    SYM(p_a, s_a);       SYM(p_mlp, g_mlp);
    SYM(p_wqkv, w_qkv);  SYM(p_wo, w_ot);     SYM(p_wd, w_dt);
#undef SYM

    // weight transposes (fp32 [K,N] -> fp16 [N,K]); q/k/v concatenated
    k_t16<<<dim3(QC / 32, HH / 32), 256>>>(wq, (f16*)p_wqkv, HH, QC);
    k_t16<<<dim3(KC / 32, HH / 32), 256>>>(wk, (f16*)p_wqkv + (size_t)QC * HH, HH, KC);
    k_t16<<<dim3(KC / 32, HH / 32), 256>>>(wv, (f16*)p_wqkv + (size_t)(QC + KC) * HH, HH, KC);
    k_t16<<<dim3(HH / 32, QC / 32), 256>>>(wo, (f16*)p_wo, QC, HH);
    k_t16gu<<<dim3(FF / 32, HH / 32, 2), 256>>>(w_gate, w_up);
    k_t16<<<dim3(HH / 32, FF / 32), 256>>>(w_down, (f16*)p_wd, FF, HH);

    // h = rmsnorm(x, g_in) -> fp16
    k_rms16<<<MROWS, 256>>>(x, gin, (f16*)p_h);

    // merged QKV projection (fp32 out)
    k_gemm<<<dim3(QKVC / 256, MROWS / 128), 512, SMEM_G1>>>(
        (f16*)p_h, (f16*)p_wqkv, (float*)p_qkv, HH, HH, HH, QKVC);

    // RoPE -> q/k fp16 hi/lo; V transpose -> fp16
    k_rope_split<<<(MROWS * 12 * 128) / 256, 256>>>();
    k_vtrans<<<dim3(HD / 32, SS / 32, BB * NKV), 256>>>();

    // scores = q @ k^T (3-pass, causal tiles only)
    k_qk<<<dim3(SS / 256, SS / 128, BB * NH), 512, SMEM_G3>>>();

    // softcap + causal + softmax -> p fp16
    k_softmax<<<BB * NH * SS, 256>>>();

    // o = p @ v (causal K-limit, fp16 out)
    k_pv<<<dim3(HD / 256, SS / 128, BB * NH), 512, SMEM_G1>>>();

    // attn_out = o @ wo
    k_gemm<<<dim3(HH / 256, MROWS / 128), 512, SMEM_G1>>>(
        (f16*)p_o, (f16*)p_wo, (float*)p_attn, QC, QC, QC, HH);

    // h2 = x + rmsnorm(attn); f = rmsnorm(h2) -> fp16
    k_add_rms<<<MROWS, 256>>>(x, (float*)p_attn, gpa, (float*)p_h2);
    k_rms16<<<MROWS, 256>>>((float*)p_h2, gpf, (f16*)p_f);

    // merged gate+up GEMM with fused GeGLU -> s_a fp16
    k_gu<<<dim3((2 * FF) / 256, MROWS / 128), 512, SMEM_G1>>>();

    // mlp = act @ w_down
    k_gemm<<<dim3(HH / 256, MROWS / 128), 512, SMEM_G1>>>(
        (f16*)p_a, (f16*)p_wd, (float*)p_mlp, FF, FF, FF, HH);

    // out = h2 + rmsnorm(mlp)
    k_add_rms<<<MROWS, 256>>>((float*)p_h2, (float*)p_mlp, gpff, out);
}